// round 2
// baseline (speedup 1.0000x reference)
#include <cuda_runtime.h>
#include <cstdint>

#define N_NODES 100000
#define N_EDGES 1600000
#define IN_DIM  256
#define HID     128
#define OUT_DIM 64

// Scratch (static device allocations — no cudaMalloc allowed)
__device__ float g_h[(size_t)N_NODES * HID];    // GEMM outputs / MLP hidden
__device__ float g_agg[(size_t)N_NODES * HID];  // aggregation accumulator
__device__ float g_dinv[N_NODES];               // degree -> rsqrt(degree)
__device__ int   g_src[N_EDGES];
__device__ int   g_dst[N_EDGES];
__device__ int   g_is64;

// ---------------------------------------------------------------------------
// Edge-index dtype detection + conversion to int32.
// If the buffer holds int64 little-endian values < 2^31, every odd 32-bit
// word of the first 256 entries is 0. For int32 index data that event has
// probability ~1e-1280. Deterministic given the input.
// ---------------------------------------------------------------------------
__global__ void k_detect(const int* __restrict__ ei32) {
    if (threadIdx.x == 0 && blockIdx.x == 0) {
        int all0 = 1;
        for (int i = 0; i < 256; i++)
            if (ei32[2 * i + 1] != 0) { all0 = 0; break; }
        g_is64 = all0;
    }
}

__global__ void k_convert(const void* __restrict__ ei) {
    int e = blockIdx.x * blockDim.x + threadIdx.x;
    if (e >= N_EDGES) return;
    int s, d;
    if (g_is64) {
        const long long* p = (const long long*)ei;
        s = (int)p[e];
        d = (int)p[e + N_EDGES];
    } else {
        const int* p = (const int*)ei;
        s = p[e];
        d = p[e + N_EDGES];
    }
    // defensive clamp: wrong answer beats illegal access
    s = min(max(s, 0), N_NODES - 1);
    d = min(max(d, 0), N_NODES - 1);
    g_src[e] = s;
    g_dst[e] = d;
}

// ---------------------------------------------------------------------------
// Degree pipeline: dinv[i] = rsqrt(1 + in_degree(i))   (self loops included)
// ---------------------------------------------------------------------------
__global__ void k_deg_init(float* deg) {
    int i = blockIdx.x * blockDim.x + threadIdx.x;
    if (i < N_NODES) deg[i] = 1.0f;  // self loop
}

__global__ void k_deg_count(const int* __restrict__ dst, float* deg) {
    int e = blockIdx.x * blockDim.x + threadIdx.x;
    if (e < N_EDGES) atomicAdd(&deg[dst[e]], 1.0f);
}

__global__ void k_deg_fin(float* deg) {
    int i = blockIdx.x * blockDim.x + threadIdx.x;
    if (i < N_NODES) deg[i] = rsqrtf(deg[i]);
}

// ---------------------------------------------------------------------------
// Tiled fp32 GEMM: C[M,N] = op(A)[M,K] @ W[K,N]  (+ optional bias / relu)
// PRE:       a = relu(a + preB[k])   applied to A elements on load
// EPI_BIAS:  c += epiB[n]
// EPI_RELU:  c = max(c, 0)
// BM=64, BN=64, BK=32, 16x16 threads, 4x4 per-thread tile.
// ---------------------------------------------------------------------------
template <bool PRE, bool EPI_BIAS, bool EPI_RELU>
__global__ void __launch_bounds__(256)
k_gemm(const float* __restrict__ A, const float* __restrict__ W,
       const float* __restrict__ preB, const float* __restrict__ epiB,
       float* __restrict__ C, int M, int K, int N)
{
    __shared__ float As[64][33];
    __shared__ float Bs[32][68];

    const int bm = blockIdx.x * 64;
    const int bn = blockIdx.y * 64;
    const int tx = threadIdx.x;       // 0..15
    const int ty = threadIdx.y;       // 0..15
    const int tid = ty * 16 + tx;     // 0..255

    float acc[4][4];
#pragma unroll
    for (int m = 0; m < 4; m++)
#pragma unroll
        for (int n = 0; n < 4; n++) acc[m][n] = 0.0f;

    for (int k0 = 0; k0 < K; k0 += 32) {
        // Load A tile (64 x 32), coalesced
#pragma unroll
        for (int i = 0; i < 8; i++) {
            int idx = i * 256 + tid;
            int r = idx >> 5, c = idx & 31;
            int grow = bm + r;
            float v = 0.0f;
            if (grow < M) {
                v = A[(size_t)grow * K + (k0 + c)];
                if (PRE) v = fmaxf(v + preB[k0 + c], 0.0f);
            }
            As[r][c] = v;
        }
        // Load W tile (32 x 64), coalesced
#pragma unroll
        for (int i = 0; i < 8; i++) {
            int idx = i * 256 + tid;
            int r = idx >> 6, c = idx & 63;
            Bs[r][c] = W[(size_t)(k0 + r) * N + (bn + c)];
        }
        __syncthreads();

#pragma unroll
        for (int kk = 0; kk < 32; kk++) {
            float a[4], b[4];
#pragma unroll
            for (int m = 0; m < 4; m++) a[m] = As[ty * 4 + m][kk];
#pragma unroll
            for (int n = 0; n < 4; n++) b[n] = Bs[kk][tx * 4 + n];
#pragma unroll
            for (int m = 0; m < 4; m++)
#pragma unroll
                for (int n = 0; n < 4; n++) acc[m][n] = fmaf(a[m], b[n], acc[m][n]);
        }
        __syncthreads();
    }

#pragma unroll
    for (int m = 0; m < 4; m++) {
        int grow = bm + ty * 4 + m;
        if (grow >= M) continue;
#pragma unroll
        for (int n = 0; n < 4; n++) {
            int gcol = bn + tx * 4 + n;
            float v = acc[m][n];
            if (EPI_BIAS) v += epiB[gcol];
            if (EPI_RELU) v = fmaxf(v, 0.0f);
            C[(size_t)grow * N + gcol] = v;
        }
    }
}

// ---------------------------------------------------------------------------
// init agg with the self-loop term: agg[i,:] = h[i,:] * dinv[i]^2
// (also serves as the zero-init before the atomic scatter)
// ---------------------------------------------------------------------------
__global__ void k_init_agg(const float* __restrict__ h,
                           const float* __restrict__ dinv,
                           float* __restrict__ agg)
{
    int idx = blockIdx.x * blockDim.x + threadIdx.x;
    if (idx >= N_NODES * (HID / 4)) return;
    int node = idx / (HID / 4);
    float di = dinv[node];
    float s = di * di;
    float4 v = ((const float4*)h)[idx];
    v.x *= s; v.y *= s; v.z *= s; v.w *= s;
    ((float4*)agg)[idx] = v;
}

// ---------------------------------------------------------------------------
// Edge scatter: one warp per edge. Lane l handles float4 chunk l of the row.
// agg[dst] += h[src] * (dinv[src]*dinv[dst])  via red.global.add.v4.f32
// ---------------------------------------------------------------------------
__global__ void __launch_bounds__(256)
k_scatter(const int* __restrict__ src_idx,
          const int* __restrict__ dst_idx,
          const float* __restrict__ h,
          const float* __restrict__ dinv,
          float* __restrict__ agg)
{
    int warp = (blockIdx.x * blockDim.x + threadIdx.x) >> 5;
    int lane = threadIdx.x & 31;
    if (warp >= N_EDGES) return;

    int s = src_idx[warp];
    int d = dst_idx[warp];
    float norm = dinv[s] * dinv[d];

    float4 v = ((const float4*)(h + (size_t)s * HID))[lane];
    v.x *= norm; v.y *= norm; v.z *= norm; v.w *= norm;

    float* ap = agg + (size_t)d * HID + lane * 4;
    asm volatile("red.global.add.v4.f32 [%0], {%1,%2,%3,%4};"
                 :: "l"(ap), "f"(v.x), "f"(v.y), "f"(v.z), "f"(v.w)
                 : "memory");
}

// ---------------------------------------------------------------------------
extern "C" void kernel_launch(void* const* d_in, const int* in_sizes, int n_in,
                              void* d_out, int out_size)
{
    const float* x   = (const float*)d_in[0];
    const void*  ei  = d_in[1];
    const float* W1  = (const float*)d_in[2];
    const float* b1  = (const float*)d_in[3];
    const float* W2  = (const float*)d_in[4];
    const float* b2  = (const float*)d_in[5];
    const float* Wf1 = (const float*)d_in[6];
    const float* bf1 = (const float*)d_in[7];
    const float* Wf2 = (const float*)d_in[8];
    const float* bf2 = (const float*)d_in[9];
    float* out = (float*)d_out;

    float *h, *agg, *dinv;
    int *src, *dst;
    cudaGetSymbolAddress((void**)&h,    g_h);
    cudaGetSymbolAddress((void**)&agg,  g_agg);
    cudaGetSymbolAddress((void**)&dinv, g_dinv);
    cudaGetSymbolAddress((void**)&src,  g_src);
    cudaGetSymbolAddress((void**)&dst,  g_dst);

    // --- edge index dtype detect + convert to int32 ---
    k_detect<<<1, 32>>>((const int*)ei);
    k_convert<<<(N_EDGES + 255) / 256, 256>>>(ei);

    // --- degrees ---
    k_deg_init<<<(N_NODES + 255) / 256, 256>>>(dinv);
    k_deg_count<<<(N_EDGES + 255) / 256, 256>>>(dst, dinv);
    k_deg_fin<<<(N_NODES + 255) / 256, 256>>>(dinv);

    dim3 tb(16, 16);
    const int gm = (N_NODES + 63) / 64;
    const int scatter_blocks = (N_EDGES * 32 + 255) / 256;
    const int init_blocks = (N_NODES * (HID / 4) + 255) / 256;

    // --- layer 1: H = X @ W1 ; AGG = scatter(H) ---
    k_gemm<false, false, false><<<dim3(gm, HID / 64), tb>>>(x, W1, nullptr, nullptr, h, N_NODES, IN_DIM, HID);
    k_init_agg<<<init_blocks, 256>>>(h, dinv, agg);
    k_scatter<<<scatter_blocks, 256>>>(src, dst, h, dinv, agg);

    // --- layer 2: H2 = relu(AGG + b1) @ W2 ; AGG2 = scatter(H2) ---
    k_gemm<true, false, false><<<dim3(gm, HID / 64), tb>>>(agg, W2, b1, nullptr, h, N_NODES, HID, HID);
    k_init_agg<<<init_blocks, 256>>>(h, dinv, agg);
    k_scatter<<<scatter_blocks, 256>>>(src, dst, h, dinv, agg);

    // --- MLP head ---
    // U = relu( relu(AGG2 + b2) @ Wf1 + bf1 )
    k_gemm<true, true, true><<<dim3(gm, HID / 64), tb>>>(agg, Wf1, b2, bf1, h, N_NODES, HID, HID);
    // OUT = U @ Wf2 + bf2
    k_gemm<false, true, false><<<dim3(gm, OUT_DIM / 64), tb>>>(h, Wf2, nullptr, bf2, out, N_NODES, HID, OUT_DIM);
}

// round 3
// speedup vs baseline: 1.4711x; 1.4711x over previous
#include <cuda_runtime.h>
#include <cstdint>

#define N_NODES 100000
#define N_EDGES 1600000
#define IN_DIM  256
#define HID     128
#define OUT_DIM 64

// Scratch (static device allocations — no cudaMalloc allowed)
__device__ float g_h[(size_t)N_NODES * HID];    // GEMM outputs / MLP hidden
__device__ float g_agg[(size_t)N_NODES * HID];  // aggregation accumulator
__device__ float g_dinv[N_NODES];               // degree -> rsqrt(degree)
__device__ int   g_src[N_EDGES];
__device__ int   g_dst[N_EDGES];
__device__ int   g_is64;

// ---------------------------------------------------------------------------
// Edge-index dtype detection (int64 vs int32; see R1 post-mortem)
// ---------------------------------------------------------------------------
__global__ void k_detect(const int* __restrict__ ei32) {
    if (threadIdx.x == 0 && blockIdx.x == 0) {
        int all0 = 1;
        for (int i = 0; i < 256; i++)
            if (ei32[2 * i + 1] != 0) { all0 = 0; break; }
        g_is64 = all0;
    }
}

__global__ void k_deg_init(float* deg) {
    int i = blockIdx.x * blockDim.x + threadIdx.x;
    if (i < N_NODES) deg[i] = 1.0f;  // self loop
}

// Fused: convert edge indices to int32 + count in-degrees
__global__ void k_convert_count(const void* __restrict__ ei, float* deg) {
    int e = blockIdx.x * blockDim.x + threadIdx.x;
    if (e >= N_EDGES) return;
    int s, d;
    if (g_is64) {
        const long long* p = (const long long*)ei;
        s = (int)p[e];
        d = (int)p[e + N_EDGES];
    } else {
        const int* p = (const int*)ei;
        s = p[e];
        d = p[e + N_EDGES];
    }
    s = min(max(s, 0), N_NODES - 1);
    d = min(max(d, 0), N_NODES - 1);
    g_src[e] = s;
    g_dst[e] = d;
    atomicAdd(&deg[d], 1.0f);
}

__global__ void k_deg_fin(float* deg) {
    int i = blockIdx.x * blockDim.x + threadIdx.x;
    if (i < N_NODES) deg[i] = rsqrtf(deg[i]);
}

// ---------------------------------------------------------------------------
// tf32 tensor-core GEMM:  C[M,BN] = op(A)[M,K] @ W[K,BN]
//   PRE:      a = relu(a + preB[k]) on A load
//   EPI_BIAS: c += epiB[n]
//   EPI_RELU: c = max(c,0)
//   INIT_AGG: also write agg[r,c] = c * dinv[r]^2  (self-loop init for scatter)
// BM=128, BK=32, grid.y==1 (BN == full N). 8 warps: 4 (m) x 2 (n).
// Warp tile m32 x (BN/2). mma.sync.m16n8k8.tf32, fp32 accumulate.
// ---------------------------------------------------------------------------
__device__ __forceinline__ unsigned f2tf32(float f) {
    unsigned u;
    asm("cvt.rna.tf32.f32 %0, %1;" : "=r"(u) : "f"(f));
    return u;
}

__device__ __forceinline__ void mma_tf32(float d[4], const unsigned a[4], const unsigned b[2]) {
    asm volatile(
        "mma.sync.aligned.m16n8k8.row.col.f32.tf32.tf32.f32 "
        "{%0,%1,%2,%3}, {%4,%5,%6,%7}, {%8,%9}, {%0,%1,%2,%3};"
        : "+f"(d[0]), "+f"(d[1]), "+f"(d[2]), "+f"(d[3])
        : "r"(a[0]), "r"(a[1]), "r"(a[2]), "r"(a[3]), "r"(b[0]), "r"(b[1]));
}

template <int BN, bool PRE, bool EPI_BIAS, bool EPI_RELU, bool INIT_AGG>
__global__ void __launch_bounds__(256)
k_gemm_tc(const float* __restrict__ A, const float* __restrict__ W,
          const float* __restrict__ preB, const float* __restrict__ epiB,
          float* __restrict__ C, float* __restrict__ agg,
          const float* __restrict__ dinv, int M, int K)
{
    constexpr int BM = 128, BK = 32;
    constexpr int WN = BN / 2;     // warp n extent
    constexpr int NT = WN / 8;     // n tiles per warp
    constexpr int AP = BK + 4;     // 36 (bank-conflict-free: (4r+q)%32 distinct)
    constexpr int BP = BN + 4;     // 132/68 -> P%32==4, conflict-free

    __shared__ unsigned As[BM * AP];
    __shared__ unsigned Bs[BK * BP];

    const int tid  = threadIdx.x;
    const int wid  = tid >> 5;
    const int lane = tid & 31;
    const int wm   = wid & 3;      // 0..3 -> 32 rows each
    const int wn   = wid >> 2;     // 0..1 -> WN cols each
    const int bm   = blockIdx.x * BM;
    const int lq   = lane & 3;     // lane%4
    const int lr   = lane >> 2;    // lane/4

    float acc[2][NT][4];
#pragma unroll
    for (int tm = 0; tm < 2; tm++)
#pragma unroll
        for (int tn = 0; tn < NT; tn++)
#pragma unroll
            for (int i = 0; i < 4; i++) acc[tm][tn][i] = 0.0f;

    for (int k0 = 0; k0 < K; k0 += BK) {
        // ---- load A tile (BM x BK), cvt to tf32 ----
#pragma unroll
        for (int p = 0; p < 4; p++) {
            int r  = p * 32 + (tid >> 3);
            int c4 = (tid & 7) * 4;
            float4 v = make_float4(0.f, 0.f, 0.f, 0.f);
            if (bm + r < M)
                v = *(const float4*)&A[(size_t)(bm + r) * K + k0 + c4];
            if (PRE) {
                v.x = fmaxf(v.x + preB[k0 + c4 + 0], 0.f);
                v.y = fmaxf(v.y + preB[k0 + c4 + 1], 0.f);
                v.z = fmaxf(v.z + preB[k0 + c4 + 2], 0.f);
                v.w = fmaxf(v.w + preB[k0 + c4 + 3], 0.f);
            }
            unsigned* dst = &As[r * AP + c4];
            dst[0] = f2tf32(v.x); dst[1] = f2tf32(v.y);
            dst[2] = f2tf32(v.z); dst[3] = f2tf32(v.w);
        }
        // ---- load W tile (BK x BN), cvt to tf32 ----
        constexpr int WLOADS = (BK * BN) / (4 * 256);
#pragma unroll
        for (int p = 0; p < WLOADS; p++) {
            int idx = p * 256 + tid;
            int kr  = idx / (BN / 4);
            int c4  = (idx % (BN / 4)) * 4;
            float4 v = *(const float4*)&W[(size_t)(k0 + kr) * BN + c4];
            unsigned* dst = &Bs[kr * BP + c4];
            dst[0] = f2tf32(v.x); dst[1] = f2tf32(v.y);
            dst[2] = f2tf32(v.z); dst[3] = f2tf32(v.w);
        }
        __syncthreads();

        // ---- 4 k-steps of 8 ----
#pragma unroll
        for (int ks = 0; ks < 4; ks++) {
            const int kk = ks * 8;
            unsigned af[2][4];
            unsigned bf[NT][2];
#pragma unroll
            for (int tm = 0; tm < 2; tm++) {
                int r = wm * 32 + tm * 16 + lr;
                af[tm][0] = As[r * AP + kk + lq];
                af[tm][1] = As[(r + 8) * AP + kk + lq];
                af[tm][2] = As[r * AP + kk + lq + 4];
                af[tm][3] = As[(r + 8) * AP + kk + lq + 4];
            }
#pragma unroll
            for (int tn = 0; tn < NT; tn++) {
                int c = wn * WN + tn * 8 + lr;
                bf[tn][0] = Bs[(kk + lq) * BP + c];
                bf[tn][1] = Bs[(kk + lq + 4) * BP + c];
            }
#pragma unroll
            for (int tm = 0; tm < 2; tm++)
#pragma unroll
                for (int tn = 0; tn < NT; tn++)
                    mma_tf32(acc[tm][tn], af[tm], bf[tn]);
        }
        __syncthreads();
    }

    // ---- epilogue ----
#pragma unroll
    for (int tm = 0; tm < 2; tm++) {
        int r0 = bm + wm * 32 + tm * 16 + lr;
#pragma unroll
        for (int half = 0; half < 2; half++) {
            int r = r0 + half * 8;
            if (r >= M) continue;
            float s = 0.f;
            if (INIT_AGG) { float di = dinv[r]; s = di * di; }
#pragma unroll
            for (int tn = 0; tn < NT; tn++) {
                int c = wn * WN + tn * 8 + lq * 2;
                float v0 = acc[tm][tn][half * 2 + 0];
                float v1 = acc[tm][tn][half * 2 + 1];
                if (EPI_BIAS) { v0 += epiB[c]; v1 += epiB[c + 1]; }
                if (EPI_RELU) { v0 = fmaxf(v0, 0.f); v1 = fmaxf(v1, 0.f); }
                C[(size_t)r * BN + c]     = v0;
                C[(size_t)r * BN + c + 1] = v1;
                if (INIT_AGG) {
                    agg[(size_t)r * BN + c]     = v0 * s;
                    agg[(size_t)r * BN + c + 1] = v1 * s;
                }
            }
        }
    }
}

// ---------------------------------------------------------------------------
// Edge scatter: one warp per edge, lane l handles float4 chunk l of the row.
// agg[dst] += h[src] * (dinv[src]*dinv[dst])  via red.global.add.v4.f32
// ---------------------------------------------------------------------------
__global__ void __launch_bounds__(256)
k_scatter(const int* __restrict__ src_idx,
          const int* __restrict__ dst_idx,
          const float* __restrict__ h,
          const float* __restrict__ dinv,
          float* __restrict__ agg)
{
    int warp = (blockIdx.x * blockDim.x + threadIdx.x) >> 5;
    int lane = threadIdx.x & 31;
    if (warp >= N_EDGES) return;

    int s = src_idx[warp];
    int d = dst_idx[warp];
    float norm = dinv[s] * dinv[d];

    float4 v = ((const float4*)(h + (size_t)s * HID))[lane];
    v.x *= norm; v.y *= norm; v.z *= norm; v.w *= norm;

    float* ap = agg + (size_t)d * HID + lane * 4;
    asm volatile("red.global.add.v4.f32 [%0], {%1,%2,%3,%4};"
                 :: "l"(ap), "f"(v.x), "f"(v.y), "f"(v.z), "f"(v.w)
                 : "memory");
}

// ---------------------------------------------------------------------------
extern "C" void kernel_launch(void* const* d_in, const int* in_sizes, int n_in,
                              void* d_out, int out_size)
{
    const float* x   = (const float*)d_in[0];
    const void*  ei  = d_in[1];
    const float* W1  = (const float*)d_in[2];
    const float* b1  = (const float*)d_in[3];
    const float* W2  = (const float*)d_in[4];
    const float* b2  = (const float*)d_in[5];
    const float* Wf1 = (const float*)d_in[6];
    const float* bf1 = (const float*)d_in[7];
    const float* Wf2 = (const float*)d_in[8];
    const float* bf2 = (const float*)d_in[9];
    float* out = (float*)d_out;

    float *h, *agg, *dinv;
    int *src, *dst;
    cudaGetSymbolAddress((void**)&h,    g_h);
    cudaGetSymbolAddress((void**)&agg,  g_agg);
    cudaGetSymbolAddress((void**)&dinv, g_dinv);
    cudaGetSymbolAddress((void**)&src,  g_src);
    cudaGetSymbolAddress((void**)&dst,  g_dst);

    // --- edge prologue: detect dtype, convert + degree count, finalize ---
    k_detect<<<1, 32>>>((const int*)ei);
    k_deg_init<<<(N_NODES + 255) / 256, 256>>>(dinv);
    k_convert_count<<<(N_EDGES + 255) / 256, 256>>>(ei, dinv);
    k_deg_fin<<<(N_NODES + 255) / 256, 256>>>(dinv);

    const int gm = (N_NODES + 127) / 128;
    const int scatter_blocks = (N_EDGES * 32 + 255) / 256;

    // --- layer 1: H = X @ W1 ; agg = H*dinv^2 ; scatter ---
    k_gemm_tc<HID, false, false, false, true><<<gm, 256>>>(
        x, W1, nullptr, nullptr, h, agg, dinv, N_NODES, IN_DIM);
    k_scatter<<<scatter_blocks, 256>>>(src, dst, h, dinv, agg);

    // --- layer 2: H = relu(agg+b1) @ W2 ; agg = H*dinv^2 ; scatter ---
    k_gemm_tc<HID, true, false, false, true><<<gm, 256>>>(
        agg, W2, b1, nullptr, h, agg, dinv, N_NODES, HID);
    k_scatter<<<scatter_blocks, 256>>>(src, dst, h, dinv, agg);

    // --- MLP head ---
    k_gemm_tc<HID, true, true, true, false><<<gm, 256>>>(
        agg, Wf1, b2, bf1, h, nullptr, nullptr, N_NODES, HID);
    k_gemm_tc<OUT_DIM, false, true, false, false><<<gm, 256>>>(
        h, Wf2, nullptr, bf2, out, nullptr, nullptr, N_NODES, HID);
}

// round 4
// speedup vs baseline: 2.4149x; 1.6415x over previous
#include <cuda_runtime.h>
#include <cstdint>

#define N_NODES 100000
#define N_EDGES 1600000
#define IN_DIM  256
#define HID     128
#define OUT_DIM 64

#define SCAN_CHUNK 1024
#define N_CHUNKS   ((N_NODES + SCAN_CHUNK - 1) / SCAN_CHUNK)   // 98

// Scratch (static device allocations — no cudaMalloc allowed)
__device__ float g_h[(size_t)N_NODES * HID];
__device__ float g_agg[(size_t)N_NODES * HID];
__device__ float g_dinv[N_NODES];
__device__ int   g_src[N_EDGES];
__device__ int   g_dst[N_EDGES];
__device__ int   g_degi[N_NODES];      // in-degree (int)
__device__ int   g_rowstart[N_NODES];  // CSR row offsets (exclusive prefix of deg)
__device__ int   g_cursor[N_NODES];    // bucket cursors
__device__ int   g_csr_src[N_EDGES];   // edges sorted by dst -> src list
__device__ int   g_bsum[N_CHUNKS];     // per-chunk sums for scan
__device__ int   g_is64;

// ---------------------------------------------------------------------------
// Edge-index dtype detection (int64 vs int32; see R1 post-mortem)
// ---------------------------------------------------------------------------
__global__ void k_detect(const int* __restrict__ ei32) {
    if (threadIdx.x == 0 && blockIdx.x == 0) {
        int all0 = 1;
        for (int i = 0; i < 256; i++)
            if (ei32[2 * i + 1] != 0) { all0 = 0; break; }
        g_is64 = all0;
    }
}

__global__ void k_zero_deg() {
    int i = blockIdx.x * blockDim.x + threadIdx.x;
    if (i < N_NODES) g_degi[i] = 0;
}

// Fused: convert edge indices to int32 + integer degree histogram
__global__ void k_convert_count(const void* __restrict__ ei) {
    int e = blockIdx.x * blockDim.x + threadIdx.x;
    if (e >= N_EDGES) return;
    int s, d;
    if (g_is64) {
        const long long* p = (const long long*)ei;
        s = (int)p[e];
        d = (int)p[e + N_EDGES];
    } else {
        const int* p = (const int*)ei;
        s = p[e];
        d = p[e + N_EDGES];
    }
    s = min(max(s, 0), N_NODES - 1);
    d = min(max(d, 0), N_NODES - 1);
    g_src[e] = s;
    g_dst[e] = d;
    atomicAdd(&g_degi[d], 1);
}

// ---- 3-kernel exclusive scan of g_degi -> g_rowstart (chunked) ----
__global__ void k_scan_sum() {       // one block per chunk: chunk sum
    __shared__ int sh[SCAN_CHUNK];
    int i = blockIdx.x * SCAN_CHUNK + threadIdx.x;
    sh[threadIdx.x] = (i < N_NODES) ? g_degi[i] : 0;
    __syncthreads();
    for (int off = SCAN_CHUNK / 2; off > 0; off >>= 1) {
        if (threadIdx.x < off) sh[threadIdx.x] += sh[threadIdx.x + off];
        __syncthreads();
    }
    if (threadIdx.x == 0) g_bsum[blockIdx.x] = sh[0];
}

__global__ void k_scan_top() {       // 1 block: exclusive scan of chunk sums
    __shared__ int sh[N_CHUNKS];
    if (threadIdx.x < N_CHUNKS) sh[threadIdx.x] = g_bsum[threadIdx.x];
    __syncthreads();
    if (threadIdx.x == 0) {
        int run = 0;
        for (int i = 0; i < N_CHUNKS; i++) { int v = sh[i]; sh[i] = run; run += v; }
    }
    __syncthreads();
    if (threadIdx.x < N_CHUNKS) g_bsum[threadIdx.x] = sh[threadIdx.x];
}

__global__ void k_scan_fin() {       // per-chunk exclusive scan + add offset
    __shared__ int sh[SCAN_CHUNK];
    int i = blockIdx.x * SCAN_CHUNK + threadIdx.x;
    int v = (i < N_NODES) ? g_degi[i] : 0;
    sh[threadIdx.x] = v;
    __syncthreads();
    // Hillis-Steele inclusive scan
    for (int off = 1; off < SCAN_CHUNK; off <<= 1) {
        int t = (threadIdx.x >= off) ? sh[threadIdx.x - off] : 0;
        __syncthreads();
        sh[threadIdx.x] += t;
        __syncthreads();
    }
    if (i < N_NODES) {
        int excl = g_bsum[blockIdx.x] + sh[threadIdx.x] - v;
        g_rowstart[i] = excl;
        g_cursor[i]   = excl;
        g_dinv[i]     = rsqrtf(1.0f + (float)g_degi[i]);  // self loop included
    }
}

// Bucket edges by dst: csr_src[pos] = src
__global__ void k_bucket() {
    int e = blockIdx.x * blockDim.x + threadIdx.x;
    if (e >= N_EDGES) return;
    int d = g_dst[e];
    int p = atomicAdd(&g_cursor[d], 1);
    g_csr_src[p] = g_src[e];
}

// ---------------------------------------------------------------------------
// tf32 tensor-core GEMM (same as R3):  C[M,BN] = op(A)[M,K] @ W[K,BN]
// ---------------------------------------------------------------------------
__device__ __forceinline__ unsigned f2tf32(float f) {
    unsigned u;
    asm("cvt.rna.tf32.f32 %0, %1;" : "=r"(u) : "f"(f));
    return u;
}

__device__ __forceinline__ void mma_tf32(float d[4], const unsigned a[4], const unsigned b[2]) {
    asm volatile(
        "mma.sync.aligned.m16n8k8.row.col.f32.tf32.tf32.f32 "
        "{%0,%1,%2,%3}, {%4,%5,%6,%7}, {%8,%9}, {%0,%1,%2,%3};"
        : "+f"(d[0]), "+f"(d[1]), "+f"(d[2]), "+f"(d[3])
        : "r"(a[0]), "r"(a[1]), "r"(a[2]), "r"(a[3]), "r"(b[0]), "r"(b[1]));
}

template <int BN, bool PRE, bool EPI_BIAS, bool EPI_RELU>
__global__ void __launch_bounds__(256)
k_gemm_tc(const float* __restrict__ A, const float* __restrict__ W,
          const float* __restrict__ preB, const float* __restrict__ epiB,
          float* __restrict__ C, int M, int K)
{
    constexpr int BM = 128, BK = 32;
    constexpr int WN = BN / 2;
    constexpr int NT = WN / 8;
    constexpr int AP = BK + 4;
    constexpr int BP = BN + 4;

    __shared__ unsigned As[BM * AP];
    __shared__ unsigned Bs[BK * BP];

    const int tid  = threadIdx.x;
    const int wid  = tid >> 5;
    const int lane = tid & 31;
    const int wm   = wid & 3;
    const int wn   = wid >> 2;
    const int bm   = blockIdx.x * BM;
    const int lq   = lane & 3;
    const int lr   = lane >> 2;

    float acc[2][NT][4];
#pragma unroll
    for (int tm = 0; tm < 2; tm++)
#pragma unroll
        for (int tn = 0; tn < NT; tn++)
#pragma unroll
            for (int i = 0; i < 4; i++) acc[tm][tn][i] = 0.0f;

    for (int k0 = 0; k0 < K; k0 += BK) {
#pragma unroll
        for (int p = 0; p < 4; p++) {
            int r  = p * 32 + (tid >> 3);
            int c4 = (tid & 7) * 4;
            float4 v = make_float4(0.f, 0.f, 0.f, 0.f);
            if (bm + r < M)
                v = *(const float4*)&A[(size_t)(bm + r) * K + k0 + c4];
            if (PRE) {
                v.x = fmaxf(v.x + preB[k0 + c4 + 0], 0.f);
                v.y = fmaxf(v.y + preB[k0 + c4 + 1], 0.f);
                v.z = fmaxf(v.z + preB[k0 + c4 + 2], 0.f);
                v.w = fmaxf(v.w + preB[k0 + c4 + 3], 0.f);
            }
            unsigned* dst = &As[r * AP + c4];
            dst[0] = f2tf32(v.x); dst[1] = f2tf32(v.y);
            dst[2] = f2tf32(v.z); dst[3] = f2tf32(v.w);
        }
        constexpr int WLOADS = (BK * BN) / (4 * 256);
#pragma unroll
        for (int p = 0; p < WLOADS; p++) {
            int idx = p * 256 + tid;
            int kr  = idx / (BN / 4);
            int c4  = (idx % (BN / 4)) * 4;
            float4 v = *(const float4*)&W[(size_t)(k0 + kr) * BN + c4];
            unsigned* dst = &Bs[kr * BP + c4];
            dst[0] = f2tf32(v.x); dst[1] = f2tf32(v.y);
            dst[2] = f2tf32(v.z); dst[3] = f2tf32(v.w);
        }
        __syncthreads();

#pragma unroll
        for (int ks = 0; ks < 4; ks++) {
            const int kk = ks * 8;
            unsigned af[2][4];
            unsigned bf[NT][2];
#pragma unroll
            for (int tm = 0; tm < 2; tm++) {
                int r = wm * 32 + tm * 16 + lr;
                af[tm][0] = As[r * AP + kk + lq];
                af[tm][1] = As[(r + 8) * AP + kk + lq];
                af[tm][2] = As[r * AP + kk + lq + 4];
                af[tm][3] = As[(r + 8) * AP + kk + lq + 4];
            }
#pragma unroll
            for (int tn = 0; tn < NT; tn++) {
                int c = wn * WN + tn * 8 + lr;
                bf[tn][0] = Bs[(kk + lq) * BP + c];
                bf[tn][1] = Bs[(kk + lq + 4) * BP + c];
            }
#pragma unroll
            for (int tm = 0; tm < 2; tm++)
#pragma unroll
                for (int tn = 0; tn < NT; tn++)
                    mma_tf32(acc[tm][tn], af[tm], bf[tn]);
        }
        __syncthreads();
    }

#pragma unroll
    for (int tm = 0; tm < 2; tm++) {
        int r0 = bm + wm * 32 + tm * 16 + lr;
#pragma unroll
        for (int half = 0; half < 2; half++) {
            int r = r0 + half * 8;
            if (r >= M) continue;
#pragma unroll
            for (int tn = 0; tn < NT; tn++) {
                int c = wn * WN + tn * 8 + lq * 2;
                float v0 = acc[tm][tn][half * 2 + 0];
                float v1 = acc[tm][tn][half * 2 + 1];
                if (EPI_BIAS) { v0 += epiB[c]; v1 += epiB[c + 1]; }
                if (EPI_RELU) { v0 = fmaxf(v0, 0.f); v1 = fmaxf(v1, 0.f); }
                C[(size_t)r * BN + c]     = v0;
                C[(size_t)r * BN + c + 1] = v1;
            }
        }
    }
}

// ---------------------------------------------------------------------------
// Gather-side aggregation: one warp per node. Lane l owns float4 chunk l.
// agg[n] = h[n]*dinv[n]^2 + sum_{s in N(n)} h[s]*dinv[s]*dinv[n]
// ---------------------------------------------------------------------------
__global__ void __launch_bounds__(256)
k_aggregate(const int* __restrict__ csr_src,
            const int* __restrict__ rowstart,
            const int* __restrict__ degi,
            const float* __restrict__ h,
            const float* __restrict__ dinv,
            float* __restrict__ agg)
{
    int n    = (blockIdx.x * blockDim.x + threadIdx.x) >> 5;
    int lane = threadIdx.x & 31;
    if (n >= N_NODES) return;

    float di = dinv[n];
    float4 acc = ((const float4*)(h + (size_t)n * HID))[lane];
    float s0 = di * di;
    acc.x *= s0; acc.y *= s0; acc.z *= s0; acc.w *= s0;

    int beg = rowstart[n];
    int cnt = degi[n];
    for (int j = 0; j < cnt; j++) {
        int s = csr_src[beg + j];            // warp-uniform broadcast load
        float norm = dinv[s] * di;
        float4 v = ((const float4*)(h + (size_t)s * HID))[lane];
        acc.x = fmaf(v.x, norm, acc.x);
        acc.y = fmaf(v.y, norm, acc.y);
        acc.z = fmaf(v.z, norm, acc.z);
        acc.w = fmaf(v.w, norm, acc.w);
    }
    ((float4*)(agg + (size_t)n * HID))[lane] = acc;
}

// ---------------------------------------------------------------------------
extern "C" void kernel_launch(void* const* d_in, const int* in_sizes, int n_in,
                              void* d_out, int out_size)
{
    const float* x   = (const float*)d_in[0];
    const void*  ei  = d_in[1];
    const float* W1  = (const float*)d_in[2];
    const float* b1  = (const float*)d_in[3];
    const float* W2  = (const float*)d_in[4];
    const float* b2  = (const float*)d_in[5];
    const float* Wf1 = (const float*)d_in[6];
    const float* bf1 = (const float*)d_in[7];
    const float* Wf2 = (const float*)d_in[8];
    const float* bf2 = (const float*)d_in[9];
    float* out = (float*)d_out;

    float *h, *agg, *dinv;
    int *csr_src, *rowstart, *degi;
    cudaGetSymbolAddress((void**)&h,        g_h);
    cudaGetSymbolAddress((void**)&agg,      g_agg);
    cudaGetSymbolAddress((void**)&dinv,     g_dinv);
    cudaGetSymbolAddress((void**)&csr_src,  g_csr_src);
    cudaGetSymbolAddress((void**)&rowstart, g_rowstart);
    cudaGetSymbolAddress((void**)&degi,     g_degi);

    // --- edge prologue: detect dtype, histogram, scan, bucket ---
    k_detect<<<1, 32>>>((const int*)ei);
    k_zero_deg<<<(N_NODES + 255) / 256, 256>>>();
    k_convert_count<<<(N_EDGES + 255) / 256, 256>>>(ei);
    k_scan_sum<<<N_CHUNKS, SCAN_CHUNK>>>();
    k_scan_top<<<1, SCAN_CHUNK>>>();
    k_scan_fin<<<N_CHUNKS, SCAN_CHUNK>>>();
    k_bucket<<<(N_EDGES + 255) / 256, 256>>>();

    const int gm = (N_NODES + 127) / 128;
    const int agg_blocks = (N_NODES * 32 + 255) / 256;

    // --- layer 1 ---
    k_gemm_tc<HID, false, false, false><<<gm, 256>>>(x, W1, nullptr, nullptr, h, N_NODES, IN_DIM);
    k_aggregate<<<agg_blocks, 256>>>(csr_src, rowstart, degi, h, dinv, agg);

    // --- layer 2 ---
    k_gemm_tc<HID, true, false, false><<<gm, 256>>>(agg, W2, b1, nullptr, h, N_NODES, HID);
    k_aggregate<<<agg_blocks, 256>>>(csr_src, rowstart, degi, h, dinv, agg);

    // --- MLP head ---
    k_gemm_tc<HID, true, true, true><<<gm, 256>>>(agg, Wf1, b2, bf1, h, N_NODES, HID);
    k_gemm_tc<OUT_DIM, false, true, false><<<gm, 256>>>(h, Wf2, nullptr, bf2, out, N_NODES, HID);
}